// round 3
// baseline (speedup 1.0000x reference)
#include <cuda_runtime.h>

#define EMB 1024
#define SEQ 2048
#define NB 2
#define NH 16
#define HDIM 64
#define MROWS (NB * SEQ)   // 4096

// ---- scratch (static device globals; no runtime allocation) ----
__device__ float g_q[(size_t)NB * NH * SEQ * HDIM];   // [B,H,T,64]
__device__ float g_k[(size_t)NB * NH * SEQ * HDIM];
__device__ float g_v[(size_t)NB * NH * SEQ * HDIM];
__device__ float g_att[(size_t)MROWS * EMB];          // [B,T,D]
__device__ float g_res[(size_t)MROWS * EMB];          // pre-LN

// ============================================================
// 128x128x8 fp32 tiled GEMM core (8x8 microtile, quadrant split)
// A: [M x 1024] row-major, B: [1024 x 1024] row-major (K x N)
// ============================================================
__device__ __forceinline__ void gemm_core_128(const float* __restrict__ A,
                                              const float* __restrict__ B,
                                              float (&acc)[8][8])
{
    __shared__ float As[8][132];   // transposed A tile, padded
    __shared__ float Bs[8][132];

    const int tid  = threadIdx.x;            // 256 threads
    const int tx   = tid & 15;
    const int ty   = tid >> 4;
    const int m0   = blockIdx.y * 128;
    const int n0   = blockIdx.x * 128;
    const int arow = tid >> 1;                // 0..127
    const int acol = (tid & 1) * 4;           // 0 or 4
    const int brow = tid >> 5;                // 0..7
    const int bcol = (tid & 31) * 4;          // 0..124

    const float* Ap = A + (size_t)(m0 + arow) * EMB + acol;
    const float* Bp = B + (size_t)brow * EMB + n0 + bcol;

    float4 av = *(const float4*)(Ap);
    float4 bv = *(const float4*)(Bp);

    for (int k0 = 0; k0 < EMB; k0 += 8) {
        As[acol + 0][arow] = av.x;
        As[acol + 1][arow] = av.y;
        As[acol + 2][arow] = av.z;
        As[acol + 3][arow] = av.w;
        *(float4*)&Bs[brow][bcol] = bv;
        __syncthreads();

        if (k0 + 8 < EMB) {     // prefetch next K-slab under compute
            av = *(const float4*)(Ap + k0 + 8);
            bv = *(const float4*)(Bp + (size_t)(k0 + 8) * EMB);
        }

#pragma unroll
        for (int kk = 0; kk < 8; kk++) {
            float a[8], b[8];
            *(float4*)(a)     = *(const float4*)&As[kk][ty * 4];
            *(float4*)(a + 4) = *(const float4*)&As[kk][64 + ty * 4];
            *(float4*)(b)     = *(const float4*)&Bs[kk][tx * 4];
            *(float4*)(b + 4) = *(const float4*)&Bs[kk][64 + tx * 4];
#pragma unroll
            for (int i = 0; i < 8; i++)
#pragma unroll
                for (int j = 0; j < 8; j++)
                    acc[i][j] = fmaf(a[i], b[j], acc[i][j]);
        }
        __syncthreads();
    }
}

// ============================================================
// Kernel 1: fused QKV projection, head-split output layout
// ============================================================
__global__ __launch_bounds__(256, 2) void gemm_qkv(
    const float* __restrict__ x,
    const float* __restrict__ Wq, const float* __restrict__ bq,
    const float* __restrict__ Wk, const float* __restrict__ bk,
    const float* __restrict__ Wv, const float* __restrict__ bv)
{
    const float* W; const float* bias; float* out;
    if (blockIdx.z == 0)      { W = Wq; bias = bq; out = g_q; }
    else if (blockIdx.z == 1) { W = Wk; bias = bk; out = g_k; }
    else                      { W = Wv; bias = bv; out = g_v; }

    float acc[8][8];
#pragma unroll
    for (int i = 0; i < 8; i++)
#pragma unroll
        for (int j = 0; j < 8; j++) acc[i][j] = 0.f;

    gemm_core_128(x, W, acc);

    const int tid = threadIdx.x;
    const int tx  = tid & 15, ty = tid >> 4;
    const int m0  = blockIdx.y * 128, n0 = blockIdx.x * 128;

#pragma unroll
    for (int qj = 0; qj < 2; qj++) {
        const int n = n0 + qj * 64 + tx * 4;
        const float4 b4 = *(const float4*)(bias + n);
        const int h  = n >> 6;
        const int dd = n & 63;
#pragma unroll
        for (int qi = 0; qi < 2; qi++)
#pragma unroll
            for (int i = 0; i < 4; i++) {
                const int m  = m0 + qi * 64 + ty * 4 + i;
                const int bb = m >> 11;          // batch (T = 2048)
                const int t  = m & 2047;
                float4 r;
                r.x = acc[qi * 4 + i][qj * 4 + 0] + b4.x;
                r.y = acc[qi * 4 + i][qj * 4 + 1] + b4.y;
                r.z = acc[qi * 4 + i][qj * 4 + 2] + b4.z;
                r.w = acc[qi * 4 + i][qj * 4 + 3] + b4.w;
                *(float4*)(out + ((size_t)((bb * NH + h) * SEQ + t) * HDIM + dd)) = r;
            }
    }
}

// ============================================================
// Kernel 2: flash attention. block = (q-tile of 64 rows, bh)
// ============================================================
__global__ __launch_bounds__(256) void flash_attn()
{
    extern __shared__ float smem[];
    float* Qs = smem;            // [64][64]
    float* Ks = smem + 4096;     // [64][64] (chunk-XOR swizzled)
    float* Vs = smem + 8192;     // [64][64]
    float* Ps = smem + 12288;    // [64][64]

    const int tid = threadIdx.x;
    const int tx  = tid & 15, ty = tid >> 4;
    const int qt  = blockIdx.x;
    const int bh  = blockIdx.y;

    const float* Qg = g_q + (size_t)bh * SEQ * HDIM + (size_t)qt * 64 * HDIM;
    const float* Kg = g_k + (size_t)bh * SEQ * HDIM;
    const float* Vg = g_v + (size_t)bh * SEQ * HDIM;

    // load Q tile (pre-scaled by 1/sqrt(64))
#pragma unroll
    for (int v = 0; v < 4; v++) {
        const int idx = (v * 256 + tid) * 4;
        float4 q = *(const float4*)(Qg + idx);
        q.x *= 0.125f; q.y *= 0.125f; q.z *= 0.125f; q.w *= 0.125f;
        *(float4*)(Qs + idx) = q;
    }

    float m_i[4], l_i[4], o[4][4];
#pragma unroll
    for (int i = 0; i < 4; i++) {
        m_i[i] = -1e30f; l_i[i] = 0.f;
#pragma unroll
        for (int j = 0; j < 4; j++) o[i][j] = 0.f;
    }

    for (int kt = 0; kt < SEQ / 64; kt++) {
        __syncthreads();   // previous tile fully consumed
        const float* Kt = Kg + (size_t)kt * 64 * HDIM;
        const float* Vt = Vg + (size_t)kt * 64 * HDIM;
#pragma unroll
        for (int v = 0; v < 4; v++) {
            const int idx = (v * 256 + tid) * 4;
            const int r   = idx >> 6;
            const int c4  = (idx >> 2) & 15;
            const int csw = (c4 ^ ((r >> 2) & 7)) * 4;   // bank-conflict-free both ways
            *(float4*)(Ks + r * 64 + csw) = *(const float4*)(Kt + idx);
            *(float4*)(Vs + idx)          = *(const float4*)(Vt + idx);
        }
        __syncthreads();

        // ---- S = Q @ K^T  (4x4 microtile per thread) ----
        float s[4][4];
#pragma unroll
        for (int i = 0; i < 4; i++)
#pragma unroll
            for (int j = 0; j < 4; j++) s[i][j] = 0.f;

#pragma unroll
        for (int d4 = 0; d4 < 16; d4++) {
            float q[4][4], k[4][4];
#pragma unroll
            for (int i = 0; i < 4; i++)
                *(float4*)&q[i][0] = *(const float4*)(Qs + (ty * 4 + i) * 64 + d4 * 4);
            const int dsw = (d4 ^ (tx & 7)) * 4;
#pragma unroll
            for (int j = 0; j < 4; j++)
                *(float4*)&k[j][0] = *(const float4*)(Ks + (tx * 4 + j) * 64 + dsw);
#pragma unroll
            for (int i = 0; i < 4; i++)
#pragma unroll
                for (int j = 0; j < 4; j++)
#pragma unroll
                    for (int d = 0; d < 4; d++)
                        s[i][j] = fmaf(q[i][d], k[j][d], s[i][j]);
        }

        // ---- online softmax (row groups = 16 lanes sharing ty) ----
#pragma unroll
        for (int i = 0; i < 4; i++) {
            float mx = fmaxf(fmaxf(s[i][0], s[i][1]), fmaxf(s[i][2], s[i][3]));
#pragma unroll
            for (int off = 8; off; off >>= 1)
                mx = fmaxf(mx, __shfl_xor_sync(0xffffffffu, mx, off));
            const float mnew  = fmaxf(m_i[i], mx);
            const float alpha = __expf(m_i[i] - mnew);
            m_i[i] = mnew;
            float rs = 0.f;
#pragma unroll
            for (int j = 0; j < 4; j++) { s[i][j] = __expf(s[i][j] - mnew); rs += s[i][j]; }
#pragma unroll
            for (int off = 8; off; off >>= 1)
                rs += __shfl_xor_sync(0xffffffffu, rs, off);
            l_i[i] = l_i[i] * alpha + rs;
#pragma unroll
            for (int j = 0; j < 4; j++) o[i][j] *= alpha;
            *(float4*)(Ps + (ty * 4 + i) * 64 + tx * 4) =
                make_float4(s[i][0], s[i][1], s[i][2], s[i][3]);
        }
        __syncthreads();

        // ---- O += P @ V ----
#pragma unroll
        for (int k4 = 0; k4 < 16; k4++) {
            float p[4][4], w[4][4];
#pragma unroll
            for (int i = 0; i < 4; i++)
                *(float4*)&p[i][0] = *(const float4*)(Ps + (ty * 4 + i) * 64 + k4 * 4);
#pragma unroll
            for (int kk = 0; kk < 4; kk++)
                *(float4*)&w[kk][0] = *(const float4*)(Vs + (k4 * 4 + kk) * 64 + tx * 4);
#pragma unroll
            for (int i = 0; i < 4; i++)
#pragma unroll
                for (int kk = 0; kk < 4; kk++)
#pragma unroll
                    for (int j = 0; j < 4; j++)
                        o[i][j] = fmaf(p[i][kk], w[kk][j], o[i][j]);
        }
    }

    // write O back into [B,T,D] layout for the output projection
    const int b = bh >> 4, h = bh & 15;
#pragma unroll
    for (int i = 0; i < 4; i++) {
        const float inv = 1.f / l_i[i];
        const int t = qt * 64 + ty * 4 + i;
        float4 r = make_float4(o[i][0] * inv, o[i][1] * inv, o[i][2] * inv, o[i][3] * inv);
        *(float4*)(g_att + (size_t)(b * SEQ + t) * EMB + h * HDIM + tx * 4) = r;
    }
}

// ============================================================
// Kernel 3: output projection + bias + residual
// ============================================================
__global__ __launch_bounds__(256, 2) void gemm_proj(
    const float* __restrict__ Wo, const float* __restrict__ bo,
    const float* __restrict__ x)
{
    float acc[8][8];
#pragma unroll
    for (int i = 0; i < 8; i++)
#pragma unroll
        for (int j = 0; j < 8; j++) acc[i][j] = 0.f;

    gemm_core_128(g_att, Wo, acc);

    const int tid = threadIdx.x;
    const int tx  = tid & 15, ty = tid >> 4;
    const int m0  = blockIdx.y * 128, n0 = blockIdx.x * 128;

#pragma unroll
    for (int qj = 0; qj < 2; qj++) {
        const int n = n0 + qj * 64 + tx * 4;
        const float4 b4 = *(const float4*)(bo + n);
#pragma unroll
        for (int qi = 0; qi < 2; qi++)
#pragma unroll
            for (int i = 0; i < 4; i++) {
                const int m = m0 + qi * 64 + ty * 4 + i;
                const float4 xr = *(const float4*)(x + (size_t)m * EMB + n);
                float4 r;
                r.x = acc[qi * 4 + i][qj * 4 + 0] + b4.x + xr.x;
                r.y = acc[qi * 4 + i][qj * 4 + 1] + b4.y + xr.y;
                r.z = acc[qi * 4 + i][qj * 4 + 2] + b4.z + xr.z;
                r.w = acc[qi * 4 + i][qj * 4 + 3] + b4.w + xr.w;
                *(float4*)(g_res + (size_t)m * EMB + n) = r;
            }
    }
}

// ============================================================
// Kernel 4: LayerNorm over last dim (1024), one block per row
// ============================================================
__global__ __launch_bounds__(256) void layernorm_k(
    const float* __restrict__ gamma, const float* __restrict__ beta,
    float* __restrict__ out)
{
    const int row = blockIdx.x;
    const int tid = threadIdx.x;
    const float* src = g_res + (size_t)row * EMB;

    const float4 v = *(const float4*)(src + tid * 4);
    float sum = v.x + v.y + v.z + v.w;
    float sq  = v.x * v.x + v.y * v.y + v.z * v.z + v.w * v.w;
#pragma unroll
    for (int off = 16; off; off >>= 1) {
        sum += __shfl_xor_sync(0xffffffffu, sum, off);
        sq  += __shfl_xor_sync(0xffffffffu, sq, off);
    }
    __shared__ float red[16];
    if ((tid & 31) == 0) { red[tid >> 5] = sum; red[8 + (tid >> 5)] = sq; }
    __syncthreads();
    float tot = 0.f, totsq = 0.f;
#pragma unroll
    for (int w = 0; w < 8; w++) { tot += red[w]; totsq += red[8 + w]; }

    const float mu  = tot * (1.f / EMB);
    const float var = totsq * (1.f / EMB) - mu * mu;
    const float inv = rsqrtf(var + 1e-5f);

    const float4 g4 = *(const float4*)(gamma + tid * 4);
    const float4 b4 = *(const float4*)(beta + tid * 4);
    float4 r;
    r.x = (v.x - mu) * inv * g4.x + b4.x;
    r.y = (v.y - mu) * inv * g4.y + b4.y;
    r.z = (v.z - mu) * inv * g4.z + b4.z;
    r.w = (v.w - mu) * inv * g4.w + b4.w;
    *(float4*)(out + (size_t)row * EMB + tid * 4) = r;
}

// ============================================================
extern "C" void kernel_launch(void* const* d_in, const int* in_sizes, int n_in,
                              void* d_out, int out_size)
{
    const float* x    = (const float*)d_in[0];
    const float* Wq   = (const float*)d_in[1];
    const float* bq   = (const float*)d_in[2];
    const float* Wk   = (const float*)d_in[3];
    const float* bk   = (const float*)d_in[4];
    const float* Wv   = (const float*)d_in[5];
    const float* bv   = (const float*)d_in[6];
    const float* Wo   = (const float*)d_in[7];
    const float* bo   = (const float*)d_in[8];
    const float* ln_g = (const float*)d_in[9];
    const float* ln_b = (const float*)d_in[10];
    float* out = (float*)d_out;

    cudaFuncSetAttribute(flash_attn, cudaFuncAttributeMaxDynamicSharedMemorySize, 64 * 1024);

    dim3 blk(256);
    gemm_qkv<<<dim3(EMB / 128, MROWS / 128, 3), blk>>>(x, Wq, bq, Wk, bk, Wv, bv);
    flash_attn<<<dim3(SEQ / 64, NB * NH), blk, 64 * 1024>>>();
    gemm_proj<<<dim3(EMB / 128, MROWS / 128), blk>>>(Wo, bo, x);
    layernorm_k<<<dim3(MROWS), blk>>>(ln_g, ln_b, out);
}

// round 5
// speedup vs baseline: 1.4304x; 1.4304x over previous
#include <cuda_runtime.h>
#include <cstdint>

#define EMB 1024
#define SEQ 2048
#define NB 2
#define NH 16
#define HDIM 64
#define MROWS (NB * SEQ)   // 4096
#define KC 32              // GEMM K-chunk
#define ASTR 36            // smem row stride (words), conflict-free

// ---- scratch (static device globals; no runtime allocation) ----
__device__ float g_q[(size_t)NB * NH * SEQ * HDIM];   // [B,H,T,64]
__device__ float g_k[(size_t)NB * NH * SEQ * HDIM];
__device__ float g_v[(size_t)NB * NH * SEQ * HDIM];
__device__ float g_att[(size_t)MROWS * EMB];          // [B,T,D]
__device__ float g_res[(size_t)MROWS * EMB];          // pre-LN
__device__ float g_wt[(size_t)4 * EMB * EMB];         // transposed weights [N][K] x4

// ============================================================
// helpers
// ============================================================
__device__ __forceinline__ uint32_t cvt_tf32(float x) {
    uint32_t r;
    asm("cvt.rna.tf32.f32 %0, %1;" : "=r"(r) : "f"(x));
    return r;
}
__device__ __forceinline__ unsigned long long fma2(unsigned long long a, unsigned long long b,
                                                   unsigned long long c) {
    unsigned long long d;
    asm("fma.rn.f32x2 %0, %1, %2, %3;" : "=l"(d) : "l"(a), "l"(b), "l"(c));
    return d;
}
__device__ __forceinline__ unsigned long long mul2(unsigned long long a, unsigned long long b) {
    unsigned long long d;
    asm("mul.rn.f32x2 %0, %1, %2;" : "=l"(d) : "l"(a), "l"(b));
    return d;
}
__device__ __forceinline__ unsigned long long pack2(float x, float y) {
    unsigned long long v;
    asm("mov.b64 %0, {%1, %2};" : "=l"(v) : "f"(x), "f"(y));
    return v;
}
__device__ __forceinline__ float2 unpack2(unsigned long long v) {
    float2 f;
    asm("mov.b64 {%0, %1}, %2;" : "=f"(f.x), "=f"(f.y) : "l"(v));
    return f;
}
__device__ __forceinline__ void mma_tf32(float (&c)[4], const uint32_t (&a)[4],
                                         const uint32_t (&b)[2]) {
    asm("mma.sync.aligned.m16n8k8.row.col.f32.tf32.tf32.f32 "
        "{%0,%1,%2,%3}, {%4,%5,%6,%7}, {%8,%9}, {%0,%1,%2,%3};"
        : "+f"(c[0]), "+f"(c[1]), "+f"(c[2]), "+f"(c[3])
        : "r"(a[0]), "r"(a[1]), "r"(a[2]), "r"(a[3]), "r"(b[0]), "r"(b[1]));
}

// ============================================================
// Kernel 0: weight transpose W[K][N] -> Wt[N][K] (4 matrices)
// ============================================================
__global__ __launch_bounds__(256) void transpose_w(
    const float* __restrict__ Wq, const float* __restrict__ Wk,
    const float* __restrict__ Wv, const float* __restrict__ Wo)
{
    const float* W = (blockIdx.z == 0) ? Wq : (blockIdx.z == 1) ? Wk
                   : (blockIdx.z == 2) ? Wv : Wo;
    float* out = g_wt + (size_t)blockIdx.z * EMB * EMB;
    __shared__ float t[32][33];
    int n = blockIdx.x * 32 + threadIdx.x;
    int k = blockIdx.y * 32 + threadIdx.y;
#pragma unroll
    for (int j = 0; j < 4; j++)
        t[threadIdx.y + j * 8][threadIdx.x] = W[(size_t)(k + j * 8) * EMB + n];
    __syncthreads();
    int k2 = blockIdx.y * 32 + threadIdx.x;
    int n2 = blockIdx.x * 32 + threadIdx.y;
#pragma unroll
    for (int j = 0; j < 4; j++)
        out[(size_t)(n2 + j * 8) * EMB + k2] = t[threadIdx.x][threadIdx.y + j * 8];
}

// ============================================================
// tf32 mma.sync GEMM core: acc[4][4][4] = A[128,1024] @ Bt[128,1024]^T tile
// A rows = M tile (row-major K), Bt rows = N tile (row-major K == B col-major)
// 8 warps: wm = (wid&1)*64, wn = (wid>>2? no: wid>>1)*32
// ============================================================
__device__ __forceinline__ void gemm_mma_core(const float* __restrict__ A,
                                              const float* __restrict__ Bt,
                                              float (&acc)[4][4][4])
{
    __shared__ uint32_t As[128 * ASTR];
    __shared__ uint32_t Bs[128 * ASTR];

    const int tid = threadIdx.x;
    const int m0 = blockIdx.y * 128;
    const int n0 = blockIdx.x * 128;
    const float* Ag = A  + (size_t)m0 * EMB;
    const float* Bg = Bt + (size_t)n0 * EMB;

    const int lane = tid & 31, wid = tid >> 5;
    const int wm = (wid & 1) * 64;
    const int wn = (wid >> 1) * 32;
    const int grp = lane >> 2;   // 0..7
    const int qd  = lane & 3;    // 0..3

    int rowi[4], coli[4];
    float4 pa[4], pb[4];
#pragma unroll
    for (int i = 0; i < 4; i++) {
        const int slot = tid + i * 256;       // 0..1023 float4 slots
        rowi[i] = slot >> 3;                  // 8 float4 per 32-wide row
        coli[i] = (slot & 7) * 4;
        pa[i] = *(const float4*)(Ag + (size_t)rowi[i] * EMB + coli[i]);
        pb[i] = *(const float4*)(Bg + (size_t)rowi[i] * EMB + coli[i]);
    }

#pragma unroll 1
    for (int s = 0; s < EMB / KC; s++) {
#pragma unroll
        for (int i = 0; i < 4; i++) {
            uint32_t* dA = &As[rowi[i] * ASTR + coli[i]];
            dA[0] = cvt_tf32(pa[i].x); dA[1] = cvt_tf32(pa[i].y);
            dA[2] = cvt_tf32(pa[i].z); dA[3] = cvt_tf32(pa[i].w);
            uint32_t* dB = &Bs[rowi[i] * ASTR + coli[i]];
            dB[0] = cvt_tf32(pb[i].x); dB[1] = cvt_tf32(pb[i].y);
            dB[2] = cvt_tf32(pb[i].z); dB[3] = cvt_tf32(pb[i].w);
        }
        __syncthreads();

        if (s + 1 < EMB / KC) {
            const int k0 = (s + 1) * KC;
#pragma unroll
            for (int i = 0; i < 4; i++) {
                pa[i] = *(const float4*)(Ag + (size_t)rowi[i] * EMB + k0 + coli[i]);
                pb[i] = *(const float4*)(Bg + (size_t)rowi[i] * EMB + k0 + coli[i]);
            }
        }

#pragma unroll
        for (int k8 = 0; k8 < KC / 8; k8++) {
            uint32_t af[4][4], bf[4][2];
#pragma unroll
            for (int mt = 0; mt < 4; mt++) {
                const uint32_t* p = &As[(wm + mt * 16 + grp) * ASTR + k8 * 8 + qd];
                af[mt][0] = p[0];
                af[mt][1] = p[8 * ASTR];
                af[mt][2] = p[4];
                af[mt][3] = p[8 * ASTR + 4];
            }
#pragma unroll
            for (int nt = 0; nt < 4; nt++) {
                const uint32_t* p = &Bs[(wn + nt * 8 + grp) * ASTR + k8 * 8 + qd];
                bf[nt][0] = p[0];
                bf[nt][1] = p[4];
            }
#pragma unroll
            for (int mt = 0; mt < 4; mt++)
#pragma unroll
                for (int nt = 0; nt < 4; nt++)
                    mma_tf32(acc[mt][nt], af[mt], bf[nt]);
        }
        __syncthreads();
    }
}

// ============================================================
// Kernel 1: QKV projection (tf32 mma), head-split output
// ============================================================
__global__ __launch_bounds__(256) void qkv_tc(
    const float* __restrict__ x,
    const float* __restrict__ bq, const float* __restrict__ bk,
    const float* __restrict__ bv)
{
    const int z = blockIdx.z;
    const float* Bt   = g_wt + (size_t)z * EMB * EMB;
    const float* bias = (z == 0) ? bq : (z == 1) ? bk : bv;
    float* out        = (z == 0) ? g_q : (z == 1) ? g_k : g_v;

    float acc[4][4][4];
#pragma unroll
    for (int a = 0; a < 4; a++)
#pragma unroll
        for (int b = 0; b < 4; b++)
#pragma unroll
            for (int c = 0; c < 4; c++) acc[a][b][c] = 0.f;

    gemm_mma_core(x, Bt, acc);

    const int lane = threadIdx.x & 31, wid = threadIdx.x >> 5;
    const int wm = (wid & 1) * 64, wn = (wid >> 1) * 32;
    const int grp = lane >> 2, qd = lane & 3;
    const int m0 = blockIdx.y * 128, n0 = blockIdx.x * 128;

#pragma unroll
    for (int nt = 0; nt < 4; nt++) {
        const int col = n0 + wn + nt * 8 + qd * 2;
        const int h = col >> 6, dd = col & 63;
        const float2 b2 = *(const float2*)(bias + col);
#pragma unroll
        for (int mt = 0; mt < 4; mt++)
#pragma unroll
            for (int half = 0; half < 2; half++) {
                const int m = m0 + wm + mt * 16 + grp + half * 8;
                const int bb = m >> 11, t = m & 2047;
                float2 r;
                r.x = acc[mt][nt][half * 2 + 0] + b2.x;
                r.y = acc[mt][nt][half * 2 + 1] + b2.y;
                *(float2*)(out + ((size_t)((bb * NH + h) * SEQ + t) * HDIM + dd)) = r;
            }
    }
}

// ============================================================
// Kernel 3: output projection (tf32 mma) + bias + residual
// ============================================================
__global__ __launch_bounds__(256) void proj_tc(
    const float* __restrict__ bo, const float* __restrict__ x)
{
    const float* Bt = g_wt + (size_t)3 * EMB * EMB;

    float acc[4][4][4];
#pragma unroll
    for (int a = 0; a < 4; a++)
#pragma unroll
        for (int b = 0; b < 4; b++)
#pragma unroll
            for (int c = 0; c < 4; c++) acc[a][b][c] = 0.f;

    gemm_mma_core(g_att, Bt, acc);

    const int lane = threadIdx.x & 31, wid = threadIdx.x >> 5;
    const int wm = (wid & 1) * 64, wn = (wid >> 1) * 32;
    const int grp = lane >> 2, qd = lane & 3;
    const int m0 = blockIdx.y * 128, n0 = blockIdx.x * 128;

#pragma unroll
    for (int nt = 0; nt < 4; nt++) {
        const int col = n0 + wn + nt * 8 + qd * 2;
        const float2 b2 = *(const float2*)(bo + col);
#pragma unroll
        for (int mt = 0; mt < 4; mt++)
#pragma unroll
            for (int half = 0; half < 2; half++) {
                const int m = m0 + wm + mt * 16 + grp + half * 8;
                const float2 x2 = *(const float2*)(x + (size_t)m * EMB + col);
                float2 r;
                r.x = acc[mt][nt][half * 2 + 0] + b2.x + x2.x;
                r.y = acc[mt][nt][half * 2 + 1] + b2.y + x2.y;
                *(float2*)(g_res + (size_t)m * EMB + col) = r;
            }
    }
}

// ============================================================
// Kernel 2: flash attention (fp32 with packed f32x2 FMA)
// ============================================================
__global__ __launch_bounds__(256) void flash_attn()
{
    extern __shared__ float fsm[];
    float* Qs = fsm;             // [64][64]
    float* Ks = fsm + 4096;      // [64][64] (chunk-XOR swizzled)
    float* Vs = fsm + 8192;      // [64][64]
    float* Ps = fsm + 12288;     // [64][64]

    const int tid = threadIdx.x;
    const int tx  = tid & 15, ty = tid >> 4;
    const int qt  = blockIdx.x;
    const int bh  = blockIdx.y;

    const float* Qg = g_q + (size_t)bh * SEQ * HDIM + (size_t)qt * 64 * HDIM;
    const float* Kg = g_k + (size_t)bh * SEQ * HDIM;
    const float* Vg = g_v + (size_t)bh * SEQ * HDIM;

#pragma unroll
    for (int v = 0; v < 4; v++) {
        const int idx = (v * 256 + tid) * 4;
        float4 q = *(const float4*)(Qg + idx);
        q.x *= 0.125f; q.y *= 0.125f; q.z *= 0.125f; q.w *= 0.125f;
        *(float4*)(Qs + idx) = q;
    }

    float m_i[4], l_i[4];
    unsigned long long o2[4][2];
#pragma unroll
    for (int i = 0; i < 4; i++) {
        m_i[i] = -1e30f; l_i[i] = 0.f;
        o2[i][0] = 0ull; o2[i][1] = 0ull;
    }

    for (int kt = 0; kt < SEQ / 64; kt++) {
        __syncthreads();
        const float* Kt = Kg + (size_t)kt * 64 * HDIM;
        const float* Vt = Vg + (size_t)kt * 64 * HDIM;
#pragma unroll
        for (int v = 0; v < 4; v++) {
            const int idx = (v * 256 + tid) * 4;
            const int r   = idx >> 6;
            const int c4  = (idx >> 2) & 15;
            const int csw = (c4 ^ ((r >> 2) & 7)) * 4;
            *(float4*)(Ks + r * 64 + csw) = *(const float4*)(Kt + idx);
            *(float4*)(Vs + idx)          = *(const float4*)(Vt + idx);
        }
        __syncthreads();

        // ---- S = Q @ K^T, packed over d pairs ----
        unsigned long long sa[4][4];
#pragma unroll
        for (int i = 0; i < 4; i++)
#pragma unroll
            for (int j = 0; j < 4; j++) sa[i][j] = 0ull;

#pragma unroll
        for (int d4 = 0; d4 < 16; d4++) {
            ulonglong2 q2[4], k2[4];
#pragma unroll
            for (int i = 0; i < 4; i++)
                q2[i] = *(const ulonglong2*)(Qs + (ty * 4 + i) * 64 + d4 * 4);
            const int dsw = (d4 ^ (tx & 7)) * 4;
#pragma unroll
            for (int j = 0; j < 4; j++)
                k2[j] = *(const ulonglong2*)(Ks + (tx * 4 + j) * 64 + dsw);
#pragma unroll
            for (int i = 0; i < 4; i++)
#pragma unroll
                for (int j = 0; j < 4; j++) {
                    sa[i][j] = fma2(q2[i].x, k2[j].x, sa[i][j]);
                    sa[i][j] = fma2(q2[i].y, k2[j].y, sa[i][j]);
                }
        }

        // ---- online softmax ----
#pragma unroll
        for (int i = 0; i < 4; i++) {
            float s[4];
#pragma unroll
            for (int j = 0; j < 4; j++) {
                const float2 f = unpack2(sa[i][j]);
                s[j] = f.x + f.y;
            }
            float mx = fmaxf(fmaxf(s[0], s[1]), fmaxf(s[2], s[3]));
#pragma unroll
            for (int off = 8; off; off >>= 1)
                mx = fmaxf(mx, __shfl_xor_sync(0xffffffffu, mx, off));
            const float mnew  = fmaxf(m_i[i], mx);
            const float alpha = __expf(m_i[i] - mnew);
            m_i[i] = mnew;
            float rs = 0.f;
#pragma unroll
            for (int j = 0; j < 4; j++) { s[j] = __expf(s[j] - mnew); rs += s[j]; }
#pragma unroll
            for (int off = 8; off; off >>= 1)
                rs += __shfl_xor_sync(0xffffffffu, rs, off);
            l_i[i] = l_i[i] * alpha + rs;
            const unsigned long long av = pack2(alpha, alpha);
            o2[i][0] = mul2(o2[i][0], av);
            o2[i][1] = mul2(o2[i][1], av);
            *(float4*)(Ps + (ty * 4 + i) * 64 + tx * 4) = make_float4(s[0], s[1], s[2], s[3]);
        }
        __syncthreads();

        // ---- O += P @ V, packed over j pairs ----
#pragma unroll
        for (int k4 = 0; k4 < 16; k4++) {
            float4 p4[4];
            ulonglong2 w2[4];
#pragma unroll
            for (int i = 0; i < 4; i++)
                p4[i] = *(const float4*)(Ps + (ty * 4 + i) * 64 + k4 * 4);
#pragma unroll
            for (int kk = 0; kk < 4; kk++)
                w2[kk] = *(const ulonglong2*)(Vs + (k4 * 4 + kk) * 64 + tx * 4);
#pragma unroll
            for (int i = 0; i < 4; i++) {
                const float pv[4] = { p4[i].x, p4[i].y, p4[i].z, p4[i].w };
#pragma unroll
                for (int kk = 0; kk < 4; kk++) {
                    const unsigned long long pp = pack2(pv[kk], pv[kk]);
                    o2[i][0] = fma2(pp, w2[kk].x, o2[i][0]);
                    o2[i][1] = fma2(pp, w2[kk].y, o2[i][1]);
                }
            }
        }
    }

    const int b = bh >> 4, h = bh & 15;
#pragma unroll
    for (int i = 0; i < 4; i++) {
        const float inv = 1.f / l_i[i];
        const int t = qt * 64 + ty * 4 + i;
        const float2 f0 = unpack2(o2[i][0]);
        const float2 f1 = unpack2(o2[i][1]);
        float4 r = make_float4(f0.x * inv, f0.y * inv, f1.x * inv, f1.y * inv);
        *(float4*)(g_att + (size_t)(b * SEQ + t) * EMB + h * HDIM + tx * 4) = r;
    }
}

// ============================================================
// Kernel 4: LayerNorm over last dim (1024), one block per row
// ============================================================
__global__ __launch_bounds__(256) void layernorm_k(
    const float* __restrict__ gamma, const float* __restrict__ beta,
    float* __restrict__ out)
{
    const int row = blockIdx.x;
    const int tid = threadIdx.x;
    const float* src = g_res + (size_t)row * EMB;

    const float4 v = *(const float4*)(src + tid * 4);
    float sum = v.x + v.y + v.z + v.w;
    float sq  = v.x * v.x + v.y * v.y + v.z * v.z + v.w * v.w;
#pragma unroll
    for (int off = 16; off; off >>= 1) {
        sum += __shfl_xor_sync(0xffffffffu, sum, off);
        sq  += __shfl_xor_sync(0xffffffffu, sq, off);
    }
    __shared__ float red[16];
    if ((tid & 31) == 0) { red[tid >> 5] = sum; red[8 + (tid >> 5)] = sq; }
    __syncthreads();
    float tot = 0.f, totsq = 0.f;
#pragma unroll
    for (int w = 0; w < 8; w++) { tot += red[w]; totsq += red[8 + w]; }

    const float mu  = tot * (1.f / EMB);
    const float var = totsq * (1.f / EMB) - mu * mu;
    const float inv = rsqrtf(var + 1e-5f);

    const float4 g4 = *(const float4*)(gamma + tid * 4);
    const float4 b4 = *(const float4*)(beta + tid * 4);
    float4 r;
    r.x = (v.x - mu) * inv * g4.x + b4.x;
    r.y = (v.y - mu) * inv * g4.y + b4.y;
    r.z = (v.z - mu) * inv * g4.z + b4.z;
    r.w = (v.w - mu) * inv * g4.w + b4.w;
    *(float4*)(out + (size_t)row * EMB + tid * 4) = r;
}

// ============================================================
extern "C" void kernel_launch(void* const* d_in, const int* in_sizes, int n_in,
                              void* d_out, int out_size)
{
    const float* x    = (const float*)d_in[0];
    const float* Wq   = (const float*)d_in[1];
    const float* bq   = (const float*)d_in[2];
    const float* Wk   = (const float*)d_in[3];
    const float* bk   = (const float*)d_in[4];
    const float* Wv   = (const float*)d_in[5];
    const float* bv   = (const float*)d_in[6];
    const float* Wo   = (const float*)d_in[7];
    const float* bo   = (const float*)d_in[8];
    const float* ln_g = (const float*)d_in[9];
    const float* ln_b = (const float*)d_in[10];
    float* out = (float*)d_out;

    cudaFuncSetAttribute(flash_attn, cudaFuncAttributeMaxDynamicSharedMemorySize, 64 * 1024);

    transpose_w<<<dim3(32, 32, 4), dim3(32, 8)>>>(Wq, Wk, Wv, Wo);
    qkv_tc<<<dim3(EMB / 128, MROWS / 128, 3), 256>>>(x, bq, bk, bv);
    flash_attn<<<dim3(SEQ / 64, NB * NH), 256, 64 * 1024>>>();
    proj_tc<<<dim3(EMB / 128, MROWS / 128), 256>>>(bo, x);
    layernorm_k<<<dim3(MROWS), 256>>>(ln_g, ln_b, out);
}

// round 7
// speedup vs baseline: 2.9759x; 2.0804x over previous
#include <cuda_runtime.h>
#include <cstdint>

#define EMB 1024
#define SEQ 2048
#define NB 2
#define NH 16
#define HDIM 64
#define MROWS (NB * SEQ)   // 4096
#define KC 32              // GEMM K-chunk
#define ASTR 36            // GEMM smem row stride (words), conflict-free

// ---- scratch (static device globals; no runtime allocation) ----
__device__ float g_q[(size_t)NB * NH * SEQ * HDIM];   // [B,H,T,64]
__device__ float g_k[(size_t)NB * NH * SEQ * HDIM];
__device__ float g_v[(size_t)NB * NH * SEQ * HDIM];
__device__ float g_att[(size_t)MROWS * EMB];          // [B,T,D]
__device__ float g_res[(size_t)MROWS * EMB];          // pre-LN
__device__ float g_wt[(size_t)4 * EMB * EMB];         // transposed weights [N][K] x4

// ============================================================
// helpers
// ============================================================
__device__ __forceinline__ uint32_t cvt_tf32(float x) {
    uint32_t r;
    asm("cvt.rna.tf32.f32 %0, %1;" : "=r"(r) : "f"(x));
    return r;
}
__device__ __forceinline__ void mma_tf32(float (&c)[4], const uint32_t (&a)[4],
                                         const uint32_t (&b)[2]) {
    asm("mma.sync.aligned.m16n8k8.row.col.f32.tf32.tf32.f32 "
        "{%0,%1,%2,%3}, {%4,%5,%6,%7}, {%8,%9}, {%0,%1,%2,%3};"
        : "+f"(c[0]), "+f"(c[1]), "+f"(c[2]), "+f"(c[3])
        : "r"(a[0]), "r"(a[1]), "r"(a[2]), "r"(a[3]), "r"(b[0]), "r"(b[1]));
}
__device__ __forceinline__ void mma_tf32_s(float (&c)[4], const uint32_t (&a)[4],
                                           uint32_t b0, uint32_t b1) {
    asm("mma.sync.aligned.m16n8k8.row.col.f32.tf32.tf32.f32 "
        "{%0,%1,%2,%3}, {%4,%5,%6,%7}, {%8,%9}, {%0,%1,%2,%3};"
        : "+f"(c[0]), "+f"(c[1]), "+f"(c[2]), "+f"(c[3])
        : "r"(a[0]), "r"(a[1]), "r"(a[2]), "r"(a[3]), "r"(b0), "r"(b1));
}
__device__ __forceinline__ void mma_tf32_u4(float (&c)[4], uint4 a,
                                            uint32_t b0, uint32_t b1) {
    asm("mma.sync.aligned.m16n8k8.row.col.f32.tf32.tf32.f32 "
        "{%0,%1,%2,%3}, {%4,%5,%6,%7}, {%8,%9}, {%0,%1,%2,%3};"
        : "+f"(c[0]), "+f"(c[1]), "+f"(c[2]), "+f"(c[3])
        : "r"(a.x), "r"(a.y), "r"(a.z), "r"(a.w), "r"(b0), "r"(b1));
}

// ============================================================
// Kernel 0: weight transpose W[K][N] -> Wt[N][K] (4 matrices)
// ============================================================
__global__ __launch_bounds__(256) void transpose_w(
    const float* __restrict__ Wq, const float* __restrict__ Wk,
    const float* __restrict__ Wv, const float* __restrict__ Wo)
{
    const float* W = (blockIdx.z == 0) ? Wq : (blockIdx.z == 1) ? Wk
                   : (blockIdx.z == 2) ? Wv : Wo;
    float* out = g_wt + (size_t)blockIdx.z * EMB * EMB;
    __shared__ float t[32][33];
    int n = blockIdx.x * 32 + threadIdx.x;
    int k = blockIdx.y * 32 + threadIdx.y;
#pragma unroll
    for (int j = 0; j < 4; j++)
        t[threadIdx.y + j * 8][threadIdx.x] = W[(size_t)(k + j * 8) * EMB + n];
    __syncthreads();
    int k2 = blockIdx.y * 32 + threadIdx.x;
    int n2 = blockIdx.x * 32 + threadIdx.y;
#pragma unroll
    for (int j = 0; j < 4; j++)
        out[(size_t)(n2 + j * 8) * EMB + k2] = t[threadIdx.x][threadIdx.y + j * 8];
}

// ============================================================
// tf32 mma.sync GEMM core (unchanged from passing round)
// ============================================================
__device__ __forceinline__ void gemm_mma_core(const float* __restrict__ A,
                                              const float* __restrict__ Bt,
                                              float (&acc)[4][4][4])
{
    __shared__ uint32_t As[128 * ASTR];
    __shared__ uint32_t Bs[128 * ASTR];

    const int tid = threadIdx.x;
    const int m0 = blockIdx.y * 128;
    const int n0 = blockIdx.x * 128;
    const float* Ag = A  + (size_t)m0 * EMB;
    const float* Bg = Bt + (size_t)n0 * EMB;

    const int lane = tid & 31, wid = tid >> 5;
    const int wm = (wid & 1) * 64;
    const int wn = (wid >> 1) * 32;
    const int grp = lane >> 2;
    const int qd  = lane & 3;

    int rowi[4], coli[4];
    float4 pa[4], pb[4];
#pragma unroll
    for (int i = 0; i < 4; i++) {
        const int slot = tid + i * 256;
        rowi[i] = slot >> 3;
        coli[i] = (slot & 7) * 4;
        pa[i] = *(const float4*)(Ag + (size_t)rowi[i] * EMB + coli[i]);
        pb[i] = *(const float4*)(Bg + (size_t)rowi[i] * EMB + coli[i]);
    }

#pragma unroll 1
    for (int s = 0; s < EMB / KC; s++) {
#pragma unroll
        for (int i = 0; i < 4; i++) {
            uint32_t* dA = &As[rowi[i] * ASTR + coli[i]];
            dA[0] = cvt_tf32(pa[i].x); dA[1] = cvt_tf32(pa[i].y);
            dA[2] = cvt_tf32(pa[i].z); dA[3] = cvt_tf32(pa[i].w);
            uint32_t* dB = &Bs[rowi[i] * ASTR + coli[i]];
            dB[0] = cvt_tf32(pb[i].x); dB[1] = cvt_tf32(pb[i].y);
            dB[2] = cvt_tf32(pb[i].z); dB[3] = cvt_tf32(pb[i].w);
        }
        __syncthreads();

        if (s + 1 < EMB / KC) {
            const int k0 = (s + 1) * KC;
#pragma unroll
            for (int i = 0; i < 4; i++) {
                pa[i] = *(const float4*)(Ag + (size_t)rowi[i] * EMB + k0 + coli[i]);
                pb[i] = *(const float4*)(Bg + (size_t)rowi[i] * EMB + k0 + coli[i]);
            }
        }

#pragma unroll
        for (int k8 = 0; k8 < KC / 8; k8++) {
            uint32_t af[4][4], bf[4][2];
#pragma unroll
            for (int mt = 0; mt < 4; mt++) {
                const uint32_t* p = &As[(wm + mt * 16 + grp) * ASTR + k8 * 8 + qd];
                af[mt][0] = p[0];
                af[mt][1] = p[8 * ASTR];
                af[mt][2] = p[4];
                af[mt][3] = p[8 * ASTR + 4];
            }
#pragma unroll
            for (int nt = 0; nt < 4; nt++) {
                const uint32_t* p = &Bs[(wn + nt * 8 + grp) * ASTR + k8 * 8 + qd];
                bf[nt][0] = p[0];
                bf[nt][1] = p[4];
            }
#pragma unroll
            for (int mt = 0; mt < 4; mt++)
#pragma unroll
                for (int nt = 0; nt < 4; nt++)
                    mma_tf32(acc[mt][nt], af[mt], bf[nt]);
        }
        __syncthreads();
    }
}

// ============================================================
// Kernel 1: QKV projection (tf32 mma), head-split output
// ============================================================
__global__ __launch_bounds__(256) void qkv_tc(
    const float* __restrict__ x,
    const float* __restrict__ bq, const float* __restrict__ bk,
    const float* __restrict__ bv)
{
    const int z = blockIdx.z;
    const float* Bt   = g_wt + (size_t)z * EMB * EMB;
    const float* bias = (z == 0) ? bq : (z == 1) ? bk : bv;
    float* out        = (z == 0) ? g_q : (z == 1) ? g_k : g_v;

    float acc[4][4][4];
#pragma unroll
    for (int a = 0; a < 4; a++)
#pragma unroll
        for (int b = 0; b < 4; b++)
#pragma unroll
            for (int c = 0; c < 4; c++) acc[a][b][c] = 0.f;

    gemm_mma_core(x, Bt, acc);

    const int lane = threadIdx.x & 31, wid = threadIdx.x >> 5;
    const int wm = (wid & 1) * 64, wn = (wid >> 1) * 32;
    const int grp = lane >> 2, qd = lane & 3;
    const int m0 = blockIdx.y * 128, n0 = blockIdx.x * 128;

#pragma unroll
    for (int nt = 0; nt < 4; nt++) {
        const int col = n0 + wn + nt * 8 + qd * 2;
        const int h = col >> 6, dd = col & 63;
        const float2 b2 = *(const float2*)(bias + col);
#pragma unroll
        for (int mt = 0; mt < 4; mt++)
#pragma unroll
            for (int half = 0; half < 2; half++) {
                const int m = m0 + wm + mt * 16 + grp + half * 8;
                const int bb = m >> 11, t = m & 2047;
                float2 r;
                r.x = acc[mt][nt][half * 2 + 0] + b2.x;
                r.y = acc[mt][nt][half * 2 + 1] + b2.y;
                *(float2*)(out + ((size_t)((bb * NH + h) * SEQ + t) * HDIM + dd)) = r;
            }
    }
}

// ============================================================
// Kernel 3: output projection (tf32 mma) + bias + residual
// ============================================================
__global__ __launch_bounds__(256) void proj_tc(
    const float* __restrict__ bo, const float* __restrict__ x)
{
    const float* Bt = g_wt + (size_t)3 * EMB * EMB;

    float acc[4][4][4];
#pragma unroll
    for (int a = 0; a < 4; a++)
#pragma unroll
        for (int b = 0; b < 4; b++)
#pragma unroll
            for (int c = 0; c < 4; c++) acc[a][b][c] = 0.f;

    gemm_mma_core(g_att, Bt, acc);

    const int lane = threadIdx.x & 31, wid = threadIdx.x >> 5;
    const int wm = (wid & 1) * 64, wn = (wid >> 1) * 32;
    const int grp = lane >> 2, qd = lane & 3;
    const int m0 = blockIdx.y * 128, n0 = blockIdx.x * 128;

#pragma unroll
    for (int nt = 0; nt < 4; nt++) {
        const int col = n0 + wn + nt * 8 + qd * 2;
        const float2 b2 = *(const float2*)(bo + col);
#pragma unroll
        for (int mt = 0; mt < 4; mt++)
#pragma unroll
            for (int half = 0; half < 2; half++) {
                const int m = m0 + wm + mt * 16 + grp + half * 8;
                const float2 x2 = *(const float2*)(x + (size_t)m * EMB + col);
                float2 r;
                r.x = acc[mt][nt][half * 2 + 0] + b2.x + x2.x;
                r.y = acc[mt][nt][half * 2 + 1] + b2.y + x2.y;
                *(float2*)(g_res + (size_t)m * EMB + col) = r;
            }
    }
}

// ============================================================
// Kernel 2: flash attention on tensor cores (tf32 mma.sync)
// Block: 4 warps, 128 q-rows. Warp owns 2 m-tiles (32 rows).
// smem: Qf = per-lane A-fragments (8192 w), Ks stride 68, Vs stride 72.
// ============================================================
#define QF_WORDS 8192
#define KS_OFF   QF_WORDS
#define KSTR     68
#define VS_OFF   (QF_WORDS + 64 * KSTR)
#define VSTR     72
#define FA_SMEM  ((QF_WORDS + 64 * KSTR + 64 * VSTR) * 4)

__global__ __launch_bounds__(128, 2) void flash_mma()
{
    extern __shared__ uint32_t dsm[];
    uint32_t* Qf = dsm;
    uint32_t* Ks = dsm + KS_OFF;
    uint32_t* Vs = dsm + VS_OFF;

    const int tid  = threadIdx.x;
    const int lane = tid & 31, w = tid >> 5;
    const int grp  = lane >> 2, qd = lane & 3;
    const int qt   = blockIdx.x, bh = blockIdx.y;
    const unsigned FULL = 0xffffffffu;

    const float* Qg = g_q + (size_t)bh * SEQ * HDIM + (size_t)qt * 128 * HDIM;
    const float* Kg = g_k + (size_t)bh * SEQ * HDIM;
    const float* Vg = g_v + (size_t)bh * SEQ * HDIM;

    // ---- Q A-fragments, tf32, pre-scaled; lane-private in smem ----
#pragma unroll
    for (int mt = 0; mt < 2; mt++)
#pragma unroll
        for (int k8 = 0; k8 < 8; k8++) {
            const int r = w * 32 + mt * 16 + grp;
            const int c = k8 * 8 + qd;
            uint4 f;
            f.x = cvt_tf32(0.125f * Qg[r * 64 + c]);
            f.y = cvt_tf32(0.125f * Qg[(r + 8) * 64 + c]);
            f.z = cvt_tf32(0.125f * Qg[r * 64 + c + 4]);
            f.w = cvt_tf32(0.125f * Qg[(r + 8) * 64 + c + 4]);
            *(uint4*)(Qf + ((w * 2 + mt) * 8 + k8) * 128 + lane * 4) = f;
        }

    float m_i[2][2], l_i[2][2], oacc[2][8][4];
#pragma unroll
    for (int mt = 0; mt < 2; mt++)
#pragma unroll
        for (int hh = 0; hh < 2; hh++) { m_i[mt][hh] = -1e30f; l_i[mt][hh] = 0.f; }
#pragma unroll
    for (int mt = 0; mt < 2; mt++)
#pragma unroll
        for (int nt = 0; nt < 8; nt++)
#pragma unroll
            for (int j = 0; j < 4; j++) oacc[mt][nt][j] = 0.f;

    const int src0 = (lane & ~3) | (qd >> 1);
    const int src1 = src0 + 2;
    const bool odd = qd & 1;

#pragma unroll 1
    for (int kt = 0; kt < SEQ / 64; kt++) {
        __syncthreads();                    // previous K/V tiles consumed
        const float* Kt = Kg + (size_t)kt * 64 * HDIM;
        const float* Vt = Vg + (size_t)kt * 64 * HDIM;
#pragma unroll
        for (int i = 0; i < 8; i++) {
            const int idx = tid + i * 128;
            const int r = idx >> 4, c4 = (idx & 15) * 4;
            const float4 kv = *(const float4*)(Kt + r * 64 + c4);
            uint4 kk;
            kk.x = cvt_tf32(kv.x); kk.y = cvt_tf32(kv.y);
            kk.z = cvt_tf32(kv.z); kk.w = cvt_tf32(kv.w);
            *(uint4*)(Ks + r * KSTR + c4) = kk;
            const float4 vv = *(const float4*)(Vt + r * 64 + c4);
            uint4 vk;
            vk.x = cvt_tf32(vv.x); vk.y = cvt_tf32(vv.y);
            vk.z = cvt_tf32(vv.z); vk.w = cvt_tf32(vv.w);
            *(uint4*)(Vs + r * VSTR + c4) = vk;
        }
        __syncthreads();

        // ---- S = Q @ K^T (tensor) ----
        float sacc[2][8][4];
#pragma unroll
        for (int mt = 0; mt < 2; mt++)
#pragma unroll
            for (int nt = 0; nt < 8; nt++)
#pragma unroll
                for (int j = 0; j < 4; j++) sacc[mt][nt][j] = 0.f;

#pragma unroll
        for (int k8 = 0; k8 < 8; k8++) {
            const uint4 a0 = *(const uint4*)(Qf + ((w * 2 + 0) * 8 + k8) * 128 + lane * 4);
            const uint4 a1 = *(const uint4*)(Qf + ((w * 2 + 1) * 8 + k8) * 128 + lane * 4);
#pragma unroll
            for (int nt = 0; nt < 8; nt++) {
                const uint32_t b0 = Ks[(nt * 8 + grp) * KSTR + k8 * 8 + qd];
                const uint32_t b1 = Ks[(nt * 8 + grp) * KSTR + k8 * 8 + qd + 4];
                mma_tf32_u4(sacc[0][nt], a0, b0, b1);
                mma_tf32_u4(sacc[1][nt], a1, b0, b1);
            }
        }

        // ---- online softmax (rows split by grp/half; reduce across qd lanes) ----
#pragma unroll
        for (int mt = 0; mt < 2; mt++)
#pragma unroll
            for (int hh = 0; hh < 2; hh++) {
                float mx = -1e30f;
#pragma unroll
                for (int nt = 0; nt < 8; nt++)
                    mx = fmaxf(mx, fmaxf(sacc[mt][nt][hh * 2], sacc[mt][nt][hh * 2 + 1]));
                mx = fmaxf(mx, __shfl_xor_sync(FULL, mx, 1));
                mx = fmaxf(mx, __shfl_xor_sync(FULL, mx, 2));
                const float mnew  = fmaxf(m_i[mt][hh], mx);
                const float alpha = __expf(m_i[mt][hh] - mnew);
                m_i[mt][hh] = mnew;
                float rs = 0.f;
#pragma unroll
                for (int nt = 0; nt < 8; nt++) {
                    // round P to tf32 BEFORE summing l: P/l stays exactly normalized
                    const float e0 = __uint_as_float(cvt_tf32(__expf(sacc[mt][nt][hh * 2]     - mnew)));
                    const float e1 = __uint_as_float(cvt_tf32(__expf(sacc[mt][nt][hh * 2 + 1] - mnew)));
                    sacc[mt][nt][hh * 2]     = e0;
                    sacc[mt][nt][hh * 2 + 1] = e1;
                    rs += e0 + e1;
                }
                rs += __shfl_xor_sync(FULL, rs, 1);
                rs += __shfl_xor_sync(FULL, rs, 2);
                l_i[mt][hh] = l_i[mt][hh] * alpha + rs;
#pragma unroll
                for (int nt = 0; nt < 8; nt++) {
                    oacc[mt][nt][hh * 2]     *= alpha;
                    oacc[mt][nt][hh * 2 + 1] *= alpha;
                }
            }

        // ---- O += P @ V (tensor); P C-frag -> A-frag via intra-quad shfl ----
#pragma unroll
        for (int kt2 = 0; kt2 < 8; kt2++) {
            uint32_t ap[2][4];
#pragma unroll
            for (int mt = 0; mt < 2; mt++) {
                const float v0 = __shfl_sync(FULL, sacc[mt][kt2][0], src0);
                const float v1 = __shfl_sync(FULL, sacc[mt][kt2][1], src0);
                const float v2 = __shfl_sync(FULL, sacc[mt][kt2][2], src0);
                const float v3 = __shfl_sync(FULL, sacc[mt][kt2][3], src0);
                const float u0 = __shfl_sync(FULL, sacc[mt][kt2][0], src1);
                const float u1 = __shfl_sync(FULL, sacc[mt][kt2][1], src1);
                const float u2 = __shfl_sync(FULL, sacc[mt][kt2][2], src1);
                const float u3 = __shfl_sync(FULL, sacc[mt][kt2][3], src1);
                ap[mt][0] = __float_as_uint(odd ? v1 : v0);
                ap[mt][1] = __float_as_uint(odd ? v3 : v2);
                ap[mt][2] = __float_as_uint(odd ? u1 : u0);
                ap[mt][3] = __float_as_uint(odd ? u3 : u2);
            }
#pragma unroll
            for (int nt = 0; nt < 8; nt++) {
                const uint32_t b0 = Vs[(kt2 * 8 + qd) * VSTR + nt * 8 + grp];
                const uint32_t b1 = Vs[(kt2 * 8 + qd + 4) * VSTR + nt * 8 + grp];
                mma_tf32_s(oacc[0][nt], ap[0], b0, b1);
                mma_tf32_s(oacc[1][nt], ap[1], b0, b1);
            }
        }
    }

    // ---- epilogue: normalize, write [B,T,D] for output projection ----
    const int b = bh >> 4, hd = bh & 15;
#pragma unroll
    for (int mt = 0; mt < 2; mt++)
#pragma unroll
        for (int hh = 0; hh < 2; hh++) {
            const float inv = 1.f / l_i[mt][hh];
            const int t = qt * 128 + w * 32 + mt * 16 + grp + hh * 8;
#pragma unroll
            for (int nt = 0; nt < 8; nt++) {
                float2 r;
                r.x = oacc[mt][nt][hh * 2]     * inv;
                r.y = oacc[mt][nt][hh * 2 + 1] * inv;
                *(float2*)(g_att + (size_t)(b * SEQ + t) * EMB + hd * 64 + nt * 8 + qd * 2) = r;
            }
        }
}

// ============================================================
// Kernel 4: LayerNorm over last dim (1024), one block per row
// ============================================================
__global__ __launch_bounds__(256) void layernorm_k(
    const float* __restrict__ gamma, const float* __restrict__ beta,
    float* __restrict__ out)
{
    const int row = blockIdx.x;
    const int tid = threadIdx.x;
    const float* src = g_res + (size_t)row * EMB;

    const float4 v = *(const float4*)(src + tid * 4);
    float sum = v.x + v.y + v.z + v.w;
    float sq  = v.x * v.x + v.y * v.y + v.z * v.z + v.w * v.w;
#pragma unroll
    for (int off = 16; off; off >>= 1) {
        sum += __shfl_xor_sync(0xffffffffu, sum, off);
        sq  += __shfl_xor_sync(0xffffffffu, sq, off);
    }
    __shared__ float red[16];
    if ((tid & 31) == 0) { red[tid >> 5] = sum; red[8 + (tid >> 5)] = sq; }
    __syncthreads();
    float tot = 0.f, totsq = 0.f;
#pragma unroll
    for (int w = 0; w < 8; w++) { tot += red[w]; totsq += red[8 + w]; }

    const float mu  = tot * (1.f / EMB);
    const float var = totsq * (1.f / EMB) - mu * mu;
    const float inv = rsqrtf(var + 1e-5f);

    const float4 g4 = *(const float4*)(gamma + tid * 4);
    const float4 b4 = *(const float4*)(beta + tid * 4);
    float4 r;
    r.x = (v.x - mu) * inv * g4.x + b4.x;
    r.y = (v.y - mu) * inv * g4.y + b4.y;
    r.z = (v.z - mu) * inv * g4.z + b4.z;
    r.w = (v.w - mu) * inv * g4.w + b4.w;
    *(float4*)(out + (size_t)row * EMB + tid * 4) = r;
}

// ============================================================
extern "C" void kernel_launch(void* const* d_in, const int* in_sizes, int n_in,
                              void* d_out, int out_size)
{
    const float* x    = (const float*)d_in[0];
    const float* Wq   = (const float*)d_in[1];
    const float* bq   = (const float*)d_in[2];
    const float* Wk   = (const float*)d_in[3];
    const float* bk   = (const float*)d_in[4];
    const float* Wv   = (const float*)d_in[5];
    const float* bv   = (const float*)d_in[6];
    const float* Wo   = (const float*)d_in[7];
    const float* bo   = (const float*)d_in[8];
    const float* ln_g = (const float*)d_in[9];
    const float* ln_b = (const float*)d_in[10];
    float* out = (float*)d_out;

    cudaFuncSetAttribute(flash_mma, cudaFuncAttributeMaxDynamicSharedMemorySize, FA_SMEM);

    transpose_w<<<dim3(32, 32, 4), dim3(32, 8)>>>(Wq, Wk, Wv, Wo);
    qkv_tc<<<dim3(EMB / 128, MROWS / 128, 3), 256>>>(x, bq, bk, bv);
    flash_mma<<<dim3(SEQ / 128, NB * NH), 128, FA_SMEM>>>();
    proj_tc<<<dim3(EMB / 128, MROWS / 128), 256>>>(bo, x);
    layernorm_k<<<dim3(MROWS), 256>>>(ln_g, ln_b, out);
}